// round 3
// baseline (speedup 1.0000x reference)
#include <cuda_runtime.h>
#include <cooperative_groups.h>
#include <cstdint>
#include <math.h>

namespace cg = cooperative_groups;

#define BLOCK 512
#define CLUSTER 4
#define CAP 32
#define FCAP 512

// shared-memory layout (in floats)
#define OFF_X0    0        // 3072  x buffer A (transposed: X[d*12+h])
#define OFF_X1    3072     // 3072  x buffer B
#define OFF_SCAL  6144     // 192   per-stage column scales [3][64]
#define OFF_CNT   6336     // 64    per-column correction count (int)
#define OFF_FCNT  6400     // 64    flat-list count (int, padded)
#define OFF_COLP7 6464     // 2048  correction d-index [64][CAP] (int)
#define OFF_COLC  8512     // 6144  correction values [3][64][CAP]
#define OFF_FPACK 14656    // 512   packed (d7*64+el)<<12 | k  (int)
#define OFF_FC6   15168    // 512   c6 per flat entry (int)
#define OFF_P1T   15680    // 16384 p1 tile [256][64]; becomes M cache in stage 0
#define OFF_P3T   32064    // 16384 p3 tile [256][64]; dead after stage-0 mainloop
#define OFF_RED   OFF_P3T  // 12288 partials [16][12][64] (aliases p3 tile)
#define SMEM_FLOATS 48448
#define SMEM_BYTES (SMEM_FLOATS * 4)   // 193,792 B

extern __shared__ float smem[];

__device__ __forceinline__ void cp_async16(uint32_t saddr, const void* gptr) {
    asm volatile("cp.async.cg.shared.global [%0], [%1], 16;\n"
                 :: "r"(saddr), "l"(gptr));
}

__global__ void __cluster_dims__(CLUSTER, 1, 1) __launch_bounds__(BLOCK, 1)
chain_kernel(const float* __restrict__ p1, const float* __restrict__ p2,
             const float* __restrict__ p3, const float* __restrict__ p4,
             const int* __restrict__ p5, const int* __restrict__ p6,
             const int* __restrict__ p7, const int* __restrict__ p8,
             const float* __restrict__ p9, const float* __restrict__ p10,
             const float* __restrict__ p11, const float* __restrict__ p12,
             const float* __restrict__ p13, const float* __restrict__ p14,
             const float* __restrict__ p15, const float* __restrict__ p16,
             float* __restrict__ out, int K)
{
    cg::cluster_group cluster = cg::this_cluster();
    const int tid  = (int)threadIdx.x;
    const int rank = (int)cluster.block_rank();      // 0..3
    const int b    = (int)blockIdx.x >> 2;           // batch 0..5
    const int e0   = rank * 64;                      // this CTA's column base

    float* X0     = smem + OFF_X0;
    float* X1     = smem + OFF_X1;
    float* scal   = smem + OFF_SCAL;
    float* colc   = smem + OFF_COLC;
    float* p1t    = smem + OFF_P1T;
    float* p3t    = smem + OFF_P3T;
    float* red    = smem + OFF_RED;
    int*   colcnt = (int*)(smem + OFF_CNT);
    int*   fcnt   = (int*)(smem + OFF_FCNT);
    int*   colp7  = (int*)(smem + OFF_COLP7);
    int*   fpack  = (int*)(smem + OFF_FPACK);
    int*   fc6    = (int*)(smem + OFF_FC6);

    // ---------------- 0: issue async copies of p1/p3 tiles (fire & forget) ----------
    {
        const float* g1 = p1 + b * 65536 + e0;
        const float* g3 = p3 + b * 65536 + e0;
        uint32_t s1 = (uint32_t)__cvta_generic_to_shared(p1t);
        uint32_t s3 = (uint32_t)__cvta_generic_to_shared(p3t);
        // 4096 16B-chunks per tensor; chunk c -> row c>>4, quad c&15
        #pragma unroll
        for (int it = 0; it < 8; it++) {
            int c    = tid + it * BLOCK;
            int row  = c >> 4;
            int q    = (c & 15) << 2;               // float offset within row
            cp_async16(s1 + (row * 64 + q) * 4, g1 + row * 256 + q);
            cp_async16(s3 + (row * 64 + q) * 4, g3 + row * 256 + q);
        }
        asm volatile("cp.async.commit_group;\n" ::: "memory");
    }

    // ---------------- 1: prep (overlapped with the copies) ----------------
    if (tid < 64) { colcnt[tid] = 0; if (tid == 0) fcnt[0] = 0; }

    // x0 = primals_2[h][b][:], stored transposed X0[d*12+h]
    for (int i = tid; i < 3072; i += BLOCK) {
        int h = i >> 8, d = i & 255;
        X0[d * 12 + h] = p2[h * 1536 + b * 256 + d];
    }

    if (tid < 64) {
        float fr[3] = { p9[0],  p12[0], p15[0] };
        float ph[3] = { p10[0], p13[0], p16[0] };
        float t = (float)(e0 + tid);
        #pragma unroll
        for (int s = 0; s < 3; s++) {
            float a  = t * 6.2831853071795864f;
            a = a * fr[s] + ph[s];
            float sv = sinf(a);
            float m  = sv * sv * 0.1f + 0.95f;
            scal[s * 64 + tid] = (s == 1) ? m : (1.0f / m);
        }
    }
    __syncthreads();

    // collect matching scatter entries into flat list
    for (int k = tid; k < K; k += BLOCK) {
        if (p5[k] == b) {
            int e8 = p8[k];
            if ((e8 >> 6) == rank) {
                int j = atomicAdd(fcnt, 1);
                if (j < FCAP) {
                    fpack[j] = ((p7[k] * 64 + (e8 & 63)) << 12) | k;
                    fc6[j]   = p6[k];
                }
            }
        }
    }
    asm volatile("cp.async.wait_group 0;\n" ::: "memory");
    __syncthreads();   // flat list + tiles visible

    // winner = max packed key per (d7,el); winners -> per-column lists
    {
        int n = fcnt[0]; if (n > FCAP) n = FCAP;
        for (int i = tid; i < n; i += BLOCK) {
            int me  = fpack[i];
            int key = me >> 12;
            bool win = true;
            for (int j = 0; j < n; j++) {
                int oth = fpack[j];
                if ((oth >> 12) == key && oth > me) { win = false; break; }
            }
            if (win) {
                int d7 = key >> 6, el = key & 63, c6 = fc6[i];
                float pb = p1t[d7 * 64 + el];
                int j = atomicAdd(&colcnt[el], 1);
                if (j < CAP) {
                    colp7[el * CAP + j] = d7;
                    colc[0 * 2048 + el * CAP + j] = p4 [b * 256 + c6] - pb;
                    colc[1 * 2048 + el * CAP + j] = p11[b * 256 + c6] - pb;
                    colc[2 * 2048 + el * CAP + j] = p14[b * 256 + c6] - pb;
                }
            }
        }
    }
    __syncthreads();

    // ---------------- 3-stage chain ----------------
    const int dch = tid >> 5;      // 0..15 : d chunk (16 d each)
    const int ep  = tid & 31;      // 0..31 : column pair
    const int el2 = ep * 2;

    float* McB = p1t + dch * 16 * 64 + el2;   // this thread's M lanes
    float* P3B = p3t + dch * 16 * 64 + el2;

    for (int s = 0; s < 3; s++) {
        const float* Xin  = (s & 1) ? X1 : X0;
        float*       Xout = (s & 1) ? X0 : X1;

        float acc[24];
        #pragma unroll
        for (int i = 0; i < 24; i++) acc[i] = 0.0f;

        const float4* X4 = (const float4*)(Xin + dch * 16 * 12);

        if (s == 0) {
            // read p1/p3 tiles from smem, form M, store in place, accumulate
            #pragma unroll 4
            for (int i = 0; i < 16; i++) {
                float2 a = *(const float2*)(McB + i * 64);
                float2 c = *(const float2*)(P3B + i * 64);
                float mx = fmaf(c.x, 0.975f, a.x);
                float my = fmaf(c.y, 0.975f, a.y);
                *(float2*)(McB + i * 64) = make_float2(mx, my);
                float4 xa = X4[i * 3 + 0];
                float4 xb = X4[i * 3 + 1];
                float4 xc = X4[i * 3 + 2];
                acc[0]  += xa.x * mx;  acc[1]  += xa.x * my;
                acc[2]  += xa.y * mx;  acc[3]  += xa.y * my;
                acc[4]  += xa.z * mx;  acc[5]  += xa.z * my;
                acc[6]  += xa.w * mx;  acc[7]  += xa.w * my;
                acc[8]  += xb.x * mx;  acc[9]  += xb.x * my;
                acc[10] += xb.y * mx;  acc[11] += xb.y * my;
                acc[12] += xb.z * mx;  acc[13] += xb.z * my;
                acc[14] += xb.w * mx;  acc[15] += xb.w * my;
                acc[16] += xc.x * mx;  acc[17] += xc.x * my;
                acc[18] += xc.y * mx;  acc[19] += xc.y * my;
                acc[20] += xc.z * mx;  acc[21] += xc.z * my;
                acc[22] += xc.w * mx;  acc[23] += xc.w * my;
            }
        } else {
            #pragma unroll 4
            for (int i = 0; i < 16; i++) {
                float2 m2v = *(const float2*)(McB + i * 64);
                float mx = m2v.x, my = m2v.y;
                float4 xa = X4[i * 3 + 0];
                float4 xb = X4[i * 3 + 1];
                float4 xc = X4[i * 3 + 2];
                acc[0]  += xa.x * mx;  acc[1]  += xa.x * my;
                acc[2]  += xa.y * mx;  acc[3]  += xa.y * my;
                acc[4]  += xa.z * mx;  acc[5]  += xa.z * my;
                acc[6]  += xa.w * mx;  acc[7]  += xa.w * my;
                acc[8]  += xb.x * mx;  acc[9]  += xb.x * my;
                acc[10] += xb.y * mx;  acc[11] += xb.y * my;
                acc[12] += xb.z * mx;  acc[13] += xb.z * my;
                acc[14] += xb.w * mx;  acc[15] += xb.w * my;
                acc[16] += xc.x * mx;  acc[17] += xc.x * my;
                acc[18] += xc.y * mx;  acc[19] += xc.y * my;
                acc[20] += xc.z * mx;  acc[21] += xc.z * my;
                acc[22] += xc.w * mx;  acc[23] += xc.w * my;
            }
        }

        // sparse scatter corrections (warp 0 only)
        if (dch == 0) {
            #pragma unroll
            for (int cc = 0; cc < 2; cc++) {
                int elc = el2 + cc;
                int n = colcnt[elc]; if (n > CAP) n = CAP;
                for (int j = 0; j < n; j++) {
                    int   d7 = colp7[elc * CAP + j];
                    float cv = colc[s * 2048 + elc * CAP + j];
                    const float4* xr = (const float4*)(Xin + d7 * 12);
                    float4 xa = xr[0], xb = xr[1], xc = xr[2];
                    acc[0  + cc] += xa.x * cv;  acc[2  + cc] += xa.y * cv;
                    acc[4  + cc] += xa.z * cv;  acc[6  + cc] += xa.w * cv;
                    acc[8  + cc] += xb.x * cv;  acc[10 + cc] += xb.y * cv;
                    acc[12 + cc] += xb.z * cv;  acc[14 + cc] += xb.w * cv;
                    acc[16 + cc] += xc.x * cv;  acc[18 + cc] += xc.y * cv;
                    acc[20 + cc] += xc.z * cv;  acc[22 + cc] += xc.w * cv;
                }
            }
        }

        // stage 0: p3 tile must be fully consumed before red (same memory) is written
        if (s == 0) __syncthreads();

        // write partials
        #pragma unroll
        for (int h = 0; h < 12; h++)
            *(float2*)&red[(dch * 12 + h) * 64 + el2] =
                make_float2(acc[2 * h], acc[2 * h + 1]);
        __syncthreads();

        // reduce 16 partials, apply mod scale, emit
        for (int o = tid; o < 768; o += BLOCK) {
            int h = o >> 6, elc = o & 63;
            float sum = 0.0f;
            #pragma unroll
            for (int dc = 0; dc < 16; dc++) sum += red[(dc * 12 + h) * 64 + elc];
            sum *= scal[s * 64 + elc];
            if (s < 2) Xout[(e0 + elc) * 12 + h] = sum;
            else       out[h * 1536 + b * 256 + e0 + elc] = sum;
        }

        if (s < 2) {
            cluster.sync();   // own segment of Xout visible cluster-wide
            // pull 3 peer segments (192 float4 each)
            for (int i = tid; i < 576; i += BLOCK) {
                int pidx = i / 192;
                int off  = i % 192;
                unsigned sr = (unsigned)((rank + 1 + pidx) & 3);
                float* dst = Xout + sr * 768 + off * 4;
                const float* peer = cluster.map_shared_rank(dst, sr);
                *(float4*)dst = *(const float4*)peer;
            }
            __syncthreads();
        }
    }

    cluster.sync();   // no CTA exits while peers may still read its SMEM
}

extern "C" void kernel_launch(void* const* d_in, const int* in_sizes, int n_in,
                              void* d_out, int out_size)
{
    (void)n_in; (void)out_size;
    cudaFuncSetAttribute(chain_kernel,
                         cudaFuncAttributeMaxDynamicSharedMemorySize, SMEM_BYTES);
    chain_kernel<<<6 * CLUSTER, BLOCK, SMEM_BYTES>>>(
        (const float*)d_in[0],  (const float*)d_in[1],
        (const float*)d_in[2],  (const float*)d_in[3],
        (const int*)  d_in[4],  (const int*)  d_in[5],
        (const int*)  d_in[6],  (const int*)  d_in[7],
        (const float*)d_in[8],  (const float*)d_in[9],
        (const float*)d_in[10], (const float*)d_in[11],
        (const float*)d_in[12], (const float*)d_in[13],
        (const float*)d_in[14], (const float*)d_in[15],
        (float*)d_out, in_sizes[4]);
}